// round 16
// baseline (speedup 1.0000x reference)
#include <cuda_runtime.h>
#include <cuda_fp16.h>
#include <cstdint>

#define BB 64
#define LL 1024
#define TOTAL (BB * LL)
#define DD 512
#define HH 2048
#define NHEAD 8
#define HD 64

typedef unsigned long long ull;

// ---------------- scratch (static device globals; no allocation) ----------------
__device__ __half g_zh  [(size_t)TOTAL * DD];
__device__ __half g_hidh[(size_t)TOTAL * HH];
__device__ __half g_w1t [(size_t)HH * DD];
__device__ __half g_w2t [(size_t)DD * HH];
__device__ float g_s  [BB * NHEAD * LL];
__device__ float g_hbp[(size_t)8 * BB * NHEAD * HH];
__device__ __half g_hidbarh[BB * NHEAD * HH];
__device__ float g_c2k[NHEAD];
__device__ float g_wk_effH[NHEAD * DD];
__device__ float g_w2kf[NHEAD * HH];      // fp32 w2k, h-major
__device__ float g_y  [BB * DD];
__device__ float g_hpart[BB * 8];
__device__ unsigned char g_valid[TOTAL];

// ---------------- helpers ----------------
__device__ __forceinline__ unsigned pack_h2(float lo, float hi) {
    __half2 p = __floats2half2_rn(lo, hi);
    return *reinterpret_cast<unsigned*>(&p);
}

__device__ __forceinline__ ull fma2(ull a, ull b, ull c) {
    ull d;
    asm("fma.rn.f32x2 %0, %1, %2, %3;" : "=l"(d) : "l"(a), "l"(b), "l"(c));
    return d;
}
__device__ __forceinline__ ull packf2(float lo, float hi) {
    ull d;
    asm("mov.b64 %0, {%1, %2};" : "=l"(d) : "f"(lo), "f"(hi));
    return d;
}
__device__ __forceinline__ float2 unpackf2(ull u) {
    float2 r;
    asm("mov.b64 {%0, %1}, %2;" : "=f"(r.x), "=f"(r.y) : "l"(u));
    return r;
}

__device__ __forceinline__ void mma_f16(float* c, const unsigned* a, const unsigned* b) {
    asm volatile(
        "mma.sync.aligned.m16n8k16.row.col.f32.f16.f16.f32 "
        "{%0,%1,%2,%3}, {%4,%5,%6,%7}, {%8,%9}, {%0,%1,%2,%3};\n"
        : "+f"(c[0]), "+f"(c[1]), "+f"(c[2]), "+f"(c[3])
        : "r"(a[0]), "r"(a[1]), "r"(a[2]), "r"(a[3]), "r"(b[0]), "r"(b[1]));
}

__device__ __forceinline__ void ldsm_x4(unsigned* r, unsigned addr) {
    asm volatile("ldmatrix.sync.aligned.m8n8.x4.shared.b16 {%0,%1,%2,%3}, [%4];"
                 : "=r"(r[0]), "=r"(r[1]), "=r"(r[2]), "=r"(r[3]) : "r"(addr));
}

__device__ __forceinline__ void cp16(void* smem_dst, const void* gsrc) {
    unsigned sdst = (unsigned)__cvta_generic_to_shared(smem_dst);
    asm volatile("cp.async.cg.shared.global [%0], [%1], 16;\n"
                 :: "r"(sdst), "l"(gsrc) : "memory");
}

#define CP_COMMIT() asm volatile("cp.async.commit_group;" ::: "memory")

// ---------------- fused gather + fp16 convert + valid mask ----------------
__global__ void zh_gather_kernel(const int* __restrict__ mut,
                                 const int* __restrict__ offs,
                                 const float* __restrict__ emb)
{
    int gid = blockIdx.x * blockDim.x + threadIdx.x;
    int r = gid >> 6;
    int c = (gid & 63) << 3;
    int b = r >> 10;
    int l = r & (LL - 1);
    int s = offs[b];
    int e = offs[b + 1];
    bool ok = l < (e - s);
    int t = ok ? mut[s + l] : 0;
    const float4* src = reinterpret_cast<const float4*>(emb + (size_t)t * DD + c);
    float4 v0 = src[0], v1 = src[1];
    uint4 o;
    o.x = pack_h2(v0.x, v0.y);
    o.y = pack_h2(v0.z, v0.w);
    o.z = pack_h2(v1.x, v1.y);
    o.w = pack_h2(v1.z, v1.w);
    *reinterpret_cast<uint4*>(g_zh + (size_t)r * DD + c) = o;
    if ((gid & 63) == 0) g_valid[r] = ok ? 1 : 0;
}

// ---------------- fused transpose of W1 and W2 ----------------
__global__ void wtrans2_kernel(const float* __restrict__ W1, __half* __restrict__ W1T,
                               const float* __restrict__ W2, __half* __restrict__ W2T)
{
    __shared__ float tile[32][33];
    const int tx = threadIdx.x, ty = threadIdx.y;
    int id = blockIdx.x;
    const float* W; __half* WT; int K, N, n0, k0;
    if (id < 1024) {
        W = W1; WT = W1T; K = DD; N = HH;
        n0 = (id & 63) * 32; k0 = (id >> 6) * 32;
    } else {
        id -= 1024;
        W = W2; WT = W2T; K = HH; N = DD;
        n0 = (id & 15) * 32; k0 = (id >> 4) * 32;
    }
#pragma unroll
    for (int i = 0; i < 4; i++)
        tile[ty + i * 8][tx] = W[(size_t)(k0 + ty + i * 8) * N + n0 + tx];
    __syncthreads();
#pragma unroll
    for (int i = 0; i < 4; i++)
        WT[(size_t)(n0 + ty + i * 8) * K + k0 + tx] = __float2half_rn(tile[tx][ty + i * 8]);
}

// ---------------- prep1 (1 block): qp, wk_eff (h-major), c2k ----------------
__global__ void __launch_bounds__(512)
prep1_kernel(const float* __restrict__ q,  const float* __restrict__ Wq,
             const float* __restrict__ bq, const float* __restrict__ Wk,
             const float* __restrict__ bk, const float* __restrict__ b2)
{
    __shared__ float qs[DD];
    __shared__ float qp_s[DD];
    const int j = threadIdx.x;

    qs[j] = q[j];
    __syncthreads();

    float s = bq[j];
    for (int i = 0; i < DD; i++) s += qs[i] * Wq[(size_t)i * DD + j];
    qp_s[j] = s;
    __syncthreads();

    const float* wr = Wk + (size_t)j * DD;
#pragma unroll
    for (int h = 0; h < NHEAD; h++) {
        float t = 0.f;
#pragma unroll
        for (int d = 0; d < HD; d++) t += wr[h * HD + d] * qp_s[h * HD + d];
        g_wk_effH[h * DD + j] = t;
    }
    __syncthreads();

    if (j < NHEAD) {
        float c = 0.f;
        for (int d = 0; d < HD; d++) c += bk[j * HD + d] * qp_s[j * HD + d];
        for (int i = 0; i < DD; i++) c += b2[i] * g_wk_effH[j * DD + i];
        g_c2k[j] = c;
    }
}

// ---------------- prep2 (64 blocks): w2k coalesced warp-per-row (fp32 out) ----
__global__ void __launch_bounds__(256)
prep2_kernel(const float* __restrict__ W2)
{
    __shared__ float wk_h[NHEAD][DD];
    const int tid  = threadIdx.x;
    const int warp = tid >> 5;
    const int lane = tid & 31;

    for (int i = tid; i < NHEAD * DD; i += 256)
        (&wk_h[0][0])[i] = g_wk_effH[i];
    __syncthreads();

#pragma unroll
    for (int rr = 0; rr < 4; rr++) {
        const int i = blockIdx.x * 32 + warp * 4 + rr;
        const float* wr = W2 + (size_t)i * DD;
        float acc[NHEAD];
#pragma unroll
        for (int h = 0; h < NHEAD; h++) acc[h] = 0.f;
#pragma unroll
        for (int c = 0; c < 16; c++) {
            const int jj = lane + 32 * c;
            const float w = wr[jj];
#pragma unroll
            for (int h = 0; h < NHEAD; h++) acc[h] += w * wk_h[h][jj];
        }
#pragma unroll
        for (int h = 0; h < NHEAD; h++) {
#pragma unroll
            for (int o = 16; o > 0; o >>= 1)
                acc[h] += __shfl_xor_sync(0xffffffffu, acc[h], o);
        }
        if (lane == 0) {
#pragma unroll
            for (int h = 0; h < NHEAD; h++)
                g_w2kf[h * HH + i] = acc[h];
        }
    }
}

// ---------------- fp16 GEMM (generic, optional split-K via blockIdx.z) --------
#define BK 64
#define ATILE 8192
#define STAGE (2 * ATILE)
#define NSTG 3
#define GSMEM (NSTG * STAGE * 2)   // 98304 B

template<bool HOUT, bool RELU>
__global__ void __launch_bounds__(256, 2)
f16_gemm_kernel(const __half* __restrict__ A,
                const __half* __restrict__ Bt,
                const float* __restrict__ bias, void* __restrict__ Cv,
                int N, int K, int kLen, int pstride)
{
    extern __shared__ __align__(16) __half sm[];

    const int tid  = threadIdx.x;
    const int bm   = blockIdx.y * 128;
    const int bn   = blockIdx.x * 128;
    const int kz   = blockIdx.z;
    const int koff = kz * kLen;
    const int warp = tid >> 5;
    const int lane = tid & 31;
    const int lm   = lane >> 2;
    const int lk   = lane & 3;
    const int wm   = (warp >> 2) * 64;
    const int wn   = (warp & 3) * 32;

    const unsigned smem_b = (unsigned)__cvta_generic_to_shared(sm);

    const int lrow = tid >> 3;
    const int lchk = tid & 7;
    const __half* aptr[4];
    const __half* bptr[4];
    int adst[4];
#pragma unroll
    for (int p = 0; p < 4; p++) {
        const int r = lrow + p * 32;
        aptr[p] = A  + (size_t)(bm + r) * K + koff + lchk * 8;
        bptr[p] = Bt + (size_t)(bn + r) * K + koff + lchk * 8;
        adst[p] = r * BK + ((lchk ^ (r & 7)) * 8);
    }

    int a_off[4], a_sw[4];
#pragma unroll
    for (int mt = 0; mt < 4; mt++) {
        const int r = wm + mt * 16 + (lane & 15);
        a_off[mt] = r * 128;
        a_sw[mt]  = r & 7;
    }
    const int a_hi = (lane >> 4) & 1;
    int b_off[2], b_sw[2];
#pragma unroll
    for (int pr = 0; pr < 2; pr++) {
        const int n = wn + pr * 16 + (lane & 7) + (((lane >> 4) & 1) << 3);
        b_off[pr] = n * 128;
        b_sw[pr]  = n & 7;
    }
    const int b_hi = (lane >> 3) & 1;

    float acc[4][4][4];
#pragma unroll
    for (int mt = 0; mt < 4; mt++)
#pragma unroll
        for (int nt = 0; nt < 4; nt++)
#pragma unroll
            for (int r = 0; r < 4; r++) acc[mt][nt][r] = 0.f;

    const int T = kLen / BK;

    auto load_stage = [&](int s, int t) {
        __half* As = sm + s * STAGE;
        __half* Bs = As + ATILE;
        const int kt = t * BK;
#pragma unroll
        for (int p = 0; p < 4; p++) cp16(As + adst[p], aptr[p] + kt);
#pragma unroll
        for (int p = 0; p < 4; p++) cp16(Bs + adst[p], bptr[p] + kt);
        CP_COMMIT();
    };

    load_stage(0, 0);
    load_stage(1, 1);
    asm volatile("cp.async.wait_group 1;" ::: "memory");
    __syncthreads();

    for (int t = 0; t < T; t++) {
        const int s = t % NSTG;
        if (t + 2 < T) load_stage((t + 2) % NSTG, t + 2);

        const unsigned abase = smem_b + s * (STAGE * 2);
        const unsigned bbase = abase + ATILE * 2;
#pragma unroll
        for (int kk = 0; kk < 4; kk++) {
            const int ca = 2 * kk + a_hi;
            const int cb = 2 * kk + b_hi;
            unsigned bf[2][4];
#pragma unroll
            for (int pr = 0; pr < 2; pr++)
                ldsm_x4(bf[pr], bbase + b_off[pr] + ((cb ^ b_sw[pr]) << 4));
            unsigned af[4][4];
#pragma unroll
            for (int mt = 0; mt < 4; mt++)
                ldsm_x4(af[mt], abase + a_off[mt] + ((ca ^ a_sw[mt]) << 4));
#pragma unroll
            for (int mt = 0; mt < 4; mt++)
#pragma unroll
                for (int pr = 0; pr < 2; pr++) {
                    mma_f16(acc[mt][2 * pr],     af[mt], &bf[pr][0]);
                    mma_f16(acc[mt][2 * pr + 1], af[mt], &bf[pr][2]);
                }
        }

        if (t + 2 < T)
            asm volatile("cp.async.wait_group 1;" ::: "memory");
        else
            asm volatile("cp.async.wait_group 0;" ::: "memory");
        __syncthreads();
    }

    const float bsc = (kz == 0) ? 1.f : 0.f;
#pragma unroll
    for (int mt = 0; mt < 4; mt++) {
        const int row = bm + wm + mt * 16 + lm;
#pragma unroll
        for (int nt = 0; nt < 4; nt++) {
            const int col = bn + wn + nt * 8 + lk * 2;
            const float2 bia = *reinterpret_cast<const float2*>(&bias[col]);
            float r0x = acc[mt][nt][0] + bia.x * bsc;
            float r0y = acc[mt][nt][1] + bia.y * bsc;
            float r1x = acc[mt][nt][2] + bia.x * bsc;
            float r1y = acc[mt][nt][3] + bia.y * bsc;
            if (RELU) {
                r0x = fmaxf(r0x, 0.f); r0y = fmaxf(r0y, 0.f);
                r1x = fmaxf(r1x, 0.f); r1y = fmaxf(r1y, 0.f);
            }
            if (HOUT) {
                __half* C = (__half*)Cv;
                *reinterpret_cast<unsigned*>(C + (size_t)row * N + col)       = pack_h2(r0x, r0y);
                *reinterpret_cast<unsigned*>(C + (size_t)(row + 8) * N + col) = pack_h2(r1x, r1y);
            } else {
                float* C = (float*)Cv + (size_t)kz * pstride;
                *reinterpret_cast<float2*>(C + (size_t)row * N + col)       = make_float2(r0x, r0y);
                *reinterpret_cast<float2*>(C + (size_t)(row + 8) * N + col) = make_float2(r1x, r1y);
            }
        }
    }
}

// ---------------- block reductions ----------------
__device__ __forceinline__ float block_sum(float v, float* red) {
#pragma unroll
    for (int o = 16; o > 0; o >>= 1) v += __shfl_xor_sync(0xffffffffu, v, o);
    const int wid = threadIdx.x >> 5, lid = threadIdx.x & 31;
    const int nw = blockDim.x >> 5;
    if (lid == 0) red[wid] = v;
    __syncthreads();
    if (wid == 0) {
        v = (lid < nw) ? red[lid] : 0.f;
#pragma unroll
        for (int o = 16; o > 0; o >>= 1) v += __shfl_xor_sync(0xffffffffu, v, o);
        if (lid == 0) red[0] = v;
    }
    __syncthreads();
    float r = red[0];
    __syncthreads();
    return r;
}

__device__ __forceinline__ float block_max(float v, float* red) {
#pragma unroll
    for (int o = 16; o > 0; o >>= 1) v = fmaxf(v, __shfl_xor_sync(0xffffffffu, v, o));
    const int wid = threadIdx.x >> 5, lid = threadIdx.x & 31;
    const int nw = blockDim.x >> 5;
    if (lid == 0) red[wid] = v;
    __syncthreads();
    if (wid == 0) {
        v = (lid < nw) ? red[lid] : -3.4e38f;
#pragma unroll
        for (int o = 16; o > 0; o >>= 1) v = fmaxf(v, __shfl_xor_sync(0xffffffffu, v, o));
        if (lid == 0) red[0] = v;
    }
    __syncthreads();
    float r = red[0];
    __syncthreads();
    return r;
}

// ---------------- scores: 4 rows/warp, packed f32x2 FMA, fp32 w2k smem --------
__global__ void __launch_bounds__(256)
scores2_kernel()
{
    extern __shared__ ull w2k_u[];     // [NHEAD][HH/2] packed f32x2 = 64 KB
    __shared__ float c2k_s[NHEAD];
    const int tid  = threadIdx.x;
    const int warp = tid >> 5;
    const int lane = tid & 31;

    for (int i = tid; i < NHEAD * HH / 2; i += 256)
        w2k_u[i] = reinterpret_cast<const ull*>(g_w2kf)[i];
    if (tid < NHEAD) c2k_s[tid] = g_c2k[tid];
    __syncthreads();

    const int row0 = blockIdx.x * 128;
    for (int it = 0; it < 4; it++) {
        const int rbase = row0 + it * 32 + warp * 4;
        const __half2* hp0 = reinterpret_cast<const __half2*>(g_hidh + (size_t)rbase * HH);
        ull acc2[4][NHEAD];
#pragma unroll
        for (int rr = 0; rr < 4; rr++)
#pragma unroll
            for (int h = 0; h < NHEAD; h++) acc2[rr][h] = 0ull;

#pragma unroll 2
        for (int c = 0; c < 32; c++) {
            const int p = lane + 32 * c;
            ull w[NHEAD];
#pragma unroll
            for (int h = 0; h < NHEAD; h++) w[h] = w2k_u[h * (HH / 2) + p];
#pragma unroll
            for (int rr = 0; rr < 4; rr++) {
                const float2 hf = __half22float2(hp0[(size_t)rr * (HH / 2) + p]);
                const ull h2 = packf2(hf.x, hf.y);
#pragma unroll
                for (int h = 0; h < NHEAD; h++)
                    acc2[rr][h] = fma2(h2, w[h], acc2[rr][h]);
            }
        }
#pragma unroll
        for (int rr = 0; rr < 4; rr++) {
            float acc[NHEAD];
#pragma unroll
            for (int h = 0; h < NHEAD; h++) {
                const float2 t = unpackf2(acc2[rr][h]);
                acc[h] = t.x + t.y;
#pragma unroll
                for (int o = 16; o > 0; o >>= 1)
                    acc[h] += __shfl_xor_sync(0xffffffffu, acc[h], o);
            }
            if (lane < NHEAD) {
                const int row = rbase + rr;
                const int b = row >> 10;
                const int l = row & (LL - 1);
                float s = (acc[lane] + c2k_s[lane]) * 0.125f;
                if (!g_valid[row]) s = -1e30f;
                g_s[(b * NHEAD + lane) * LL + l] = s;
            }
        }
    }
}

// ---------------- softmax ----------------
__global__ void softmax_kernel()
{
    const int bh = blockIdx.x;
    const int tid = threadIdx.x;
    __shared__ float red[32];
    float* sp = g_s + (size_t)bh * LL;

    float v0 = sp[tid], v1 = sp[tid + 256], v2 = sp[tid + 512], v3 = sp[tid + 768];
    float mx = fmaxf(fmaxf(v0, v1), fmaxf(v2, v3));
    mx = block_max(mx, red);
    float e0 = __expf(v0 - mx), e1 = __expf(v1 - mx);
    float e2 = __expf(v2 - mx), e3 = __expf(v3 - mx);
    float sum = block_sum(e0 + e1 + e2 + e3, red);
    const float inv = 1.f / sum;
    sp[tid] = e0 * inv; sp[tid + 256] = e1 * inv;
    sp[tid + 512] = e2 * inv; sp[tid + 768] = e3 * inv;
}

// ---------------- hidbar partials: grid (BB,8), 512 thr, f32x2 FMA ------------
__global__ void __launch_bounds__(512)
hidbar_kernel()
{
    const int b  = blockIdx.x;
    const int ch = blockIdx.y;
    const int tid = threadIdx.x;
    const int d0 = tid * 4;
    __shared__ float a_s[NHEAD][128];

    for (int i = tid; i < NHEAD * 128; i += 512) {
        const int h = i >> 7, l = i & 127;
        a_s[h][l] = g_s[(size_t)(b * NHEAD + h) * LL + ch * 128 + l];
    }
    __syncthreads();

    ull acc2[NHEAD][2];
#pragma unroll
    for (int h = 0; h < NHEAD; h++) {
        acc2[h][0] = 0ull;
        acc2[h][1] = 0ull;
    }

    const __half* hp = g_hidh + ((size_t)(b * LL + ch * 128)) * HH + d0;
    for (int l = 0; l < 128; l++) {
        const uint2 hv = *reinterpret_cast<const uint2*>(hp + (size_t)l * HH);
        const float2 f01 = __half22float2(*reinterpret_cast<const __half2*>(&hv.x));
        const float2 f23 = __half22float2(*reinterpret_cast<const __half2*>(&hv.y));
        const ull u01 = packf2(f01.x, f01.y);
        const ull u23 = packf2(f23.x, f23.y);
#pragma unroll
        for (int h = 0; h < NHEAD; h++) {
            const float a = a_s[h][l];
            const ull a2 = packf2(a, a);
            acc2[h][0] = fma2(a2, u01, acc2[h][0]);
            acc2[h][1] = fma2(a2, u23, acc2[h][1]);
        }
    }
#pragma unroll
    for (int h = 0; h < NHEAD; h++) {
        const float2 t0 = unpackf2(acc2[h][0]);
        const float2 t1 = unpackf2(acc2[h][1]);
        float* dst = &g_hbp[((size_t)(ch * BB * NHEAD) + b * NHEAD + h) * HH + d0];
        dst[0] = t0.x; dst[1] = t0.y; dst[2] = t1.x; dst[3] = t1.y;
    }
}

// ---------------- reduce hidbar partials (8) -> fp16 ----------------
__global__ void hbred_kernel()
{
    const int idx = blockIdx.x * blockDim.x + threadIdx.x;
    float s = 0.f;
#pragma unroll
    for (int c = 0; c < 8; c++)
        s += g_hbp[(size_t)c * BB * NHEAD * HH + idx];
    g_hidbarh[idx] = __float2half_rn(s);
}

// ---------------- fused ctx + pooled + LN (sums 4 split-K partials) -----------
__global__ void __launch_bounds__(512)
ctx_pooled_ln_kernel(const float* __restrict__ Wv, const float* __restrict__ bv,
                     const float* __restrict__ Wo, const float* __restrict__ bo,
                     const float* __restrict__ ln_g, const float* __restrict__ ln_b)
{
    const int b = blockIdx.x;
    const int j = threadIdx.x;
    __shared__ float hb[NHEAD][DD];
    __shared__ float cx[DD];
    __shared__ float red[32];

    const int psz = BB * NHEAD * DD;
    for (int i = j; i < NHEAD * DD; i += 512) {
        float s = 0.f;
#pragma unroll
        for (int c = 0; c < 4; c++)
            s += g_hbp[(size_t)c * psz + b * NHEAD * DD + i];
        (&hb[0][0])[i] = s;
    }
    __syncthreads();

    const int h = j >> 6;
    float s = bv[j];
    for (int i = 0; i < DD; i++) s += hb[h][i] * Wv[(size_t)i * DD + j];
    cx[j] = s;
    __syncthreads();

    float p = bo[j];
    for (int i = 0; i < DD; i++) p += cx[i] * Wo[(size_t)i * DD + j];

    const float mu = block_sum(p, red) * (1.f / DD);
    float dv = p - mu;
    const float var = block_sum(dv * dv, red) * (1.f / DD);
    const float rstd = rsqrtf(var + 1e-5f);
    g_y[b * DD + j] = dv * rstd * ln_g[j] + ln_b[j];
}

// ---------------- head ----------------
__global__ void head1_kernel(const float* __restrict__ Wh1, const float* __restrict__ bh1,
                             const float* __restrict__ Wh2)
{
    const int b = blockIdx.x;
    const int sl = blockIdx.y;
    const int tid = threadIdx.x;
    __shared__ float y[DD];
    __shared__ float red[32];

    y[tid]       = g_y[b * DD + tid];
    y[tid + 256] = g_y[b * DD + tid + 256];
    __syncthreads();

    const int j = sl * 256 + tid;
    float t = bh1[j];
    for (int i = 0; i < DD; i++) t += y[i] * Wh1[(size_t)i * HH + j];
    float p = fmaxf(t, 0.f) * Wh2[j];
    const float tot = block_sum(p, red);
    if (tid == 0) g_hpart[b * 8 + sl] = tot;
}

__global__ void head2_kernel(const float* __restrict__ bh2, float* __restrict__ out)
{
    const int b = threadIdx.x;
    float s = bh2[0];
#pragma unroll
    for (int i = 0; i < 8; i++) s += g_hpart[b * 8 + i];
    out[b] = s;
}

// ---------------- launcher ----------------
extern "C" void kernel_launch(void* const* d_in, const int* in_sizes, int n_in,
                              void* d_out, int out_size)
{
    const int*   mut  = (const int*)d_in[0];
    const int*   offs = (const int*)d_in[1];
    const float* emb  = (const float*)d_in[2];
    const float* W1   = (const float*)d_in[3];
    const float* b1   = (const float*)d_in[4];
    const float* W2   = (const float*)d_in[5];
    const float* b2   = (const float*)d_in[6];
    const float* q    = (const float*)d_in[7];
    const float* Wq   = (const float*)d_in[8];
    const float* bq   = (const float*)d_in[9];
    const float* Wk   = (const float*)d_in[10];
    const float* bk   = (const float*)d_in[11];
    const float* Wv   = (const float*)d_in[12];
    const float* bv   = (const float*)d_in[13];
    const float* Wo   = (const float*)d_in[14];
    const float* bo   = (const float*)d_in[15];
    const float* ln_g = (const float*)d_in[16];
    const float* ln_b = (const float*)d_in[17];
    const float* Wh1  = (const float*)d_in[18];
    const float* bh1  = (const float*)d_in[19];
    const float* Wh2  = (const float*)d_in[20];
    const float* bh2  = (const float*)d_in[21];
    float* out = (float*)d_out;

    void *p_zh, *p_hidh, *p_w1t, *p_w2t, *p_hbh, *p_hbp;
    cudaGetSymbolAddress(&p_zh,   g_zh);
    cudaGetSymbolAddress(&p_hidh, g_hidh);
    cudaGetSymbolAddress(&p_w1t,  g_w1t);
    cudaGetSymbolAddress(&p_w2t,  g_w2t);
    cudaGetSymbolAddress(&p_hbh,  g_hidbarh);
    cudaGetSymbolAddress(&p_hbp,  g_hbp);
    __half* zh   = (__half*)p_zh;
    __half* hidh = (__half*)p_hidh;
    __half* w1t  = (__half*)p_w1t;
    __half* w2t  = (__half*)p_w2t;
    __half* hbh  = (__half*)p_hbh;
    float*  hbp  = (float*)p_hbp;

    cudaFuncSetAttribute(f16_gemm_kernel<true, true>,
                         cudaFuncAttributeMaxDynamicSharedMemorySize, GSMEM);
    cudaFuncSetAttribute(f16_gemm_kernel<false, false>,
                         cudaFuncAttributeMaxDynamicSharedMemorySize, GSMEM);
    const int sc_smem = NHEAD * HH * 4;  // 65536 B
    cudaFuncSetAttribute(scores2_kernel,
                         cudaFuncAttributeMaxDynamicSharedMemorySize, sc_smem);

    // single stream; big GEMM at launch index 3 (ncu capture slot)
    wtrans2_kernel<<<2048, dim3(32, 8)>>>(W1, w1t, W2, w2t);
    zh_gather_kernel<<<(TOTAL * 64) / 256, 256>>>(mut, offs, emb);
    prep1_kernel<<<1, 512>>>(q, Wq, bq, Wk, bk, b2);

    // 3) hidh = f16(relu(zh @ W1 + b1))  [65536 x 2048], K=512
    f16_gemm_kernel<true, true><<<dim3(HH / 128, TOTAL / 128, 1), 256, GSMEM>>>(
        zh, w1t, b1, hidh, HH, DD, DD, 0);

    prep2_kernel<<<HH / 32, 256>>>(W2);

    scores2_kernel<<<TOTAL / 128, 256, sc_smem>>>();
    softmax_kernel<<<BB * NHEAD, 256>>>();

    hidbar_kernel<<<dim3(BB, 8), 512>>>();
    hbred_kernel<<<(BB * NHEAD * HH) / 256, 256>>>();

    // hbar = hidbar @ W2 + b2  — split-K x4 (fp32 partials into g_hbp)
    f16_gemm_kernel<false, false><<<dim3(DD / 128, (BB * NHEAD) / 128, 4), 256, GSMEM>>>(
        hbh, w2t, b2, hbp, DD, HH, HH / 4, BB * NHEAD * DD);

    ctx_pooled_ln_kernel<<<BB, DD>>>(Wv, bv, Wo, bo, ln_g, ln_b);
    head1_kernel<<<dim3(BB, 8), 256>>>(Wh1, bh1, Wh2);
    head2_kernel<<<1, BB>>>(bh2, out);
}

// round 17
// speedup vs baseline: 1.0873x; 1.0873x over previous
#include <cuda_runtime.h>
#include <cuda_fp16.h>
#include <cstdint>

#define BB 64
#define LL 1024
#define TOTAL (BB * LL)
#define DD 512
#define HH 2048
#define NHEAD 8
#define HD 64

// ---------------- scratch (static device globals; no allocation) ----------------
__device__ __half g_zh  [(size_t)TOTAL * DD];
__device__ __half g_hidh[(size_t)TOTAL * HH];
__device__ __half g_w1t [(size_t)HH * DD];
__device__ __half g_w2t [(size_t)DD * HH];
__device__ float g_s  [BB * NHEAD * LL];
__device__ float g_hbp[(size_t)8 * BB * NHEAD * HH];
__device__ __half g_hidbarh[BB * NHEAD * HH];
__device__ float g_qp [DD];
__device__ float g_c2k[NHEAD];
__device__ float g_wk_effH[NHEAD * DD];
__device__ __half g_w2kh[NHEAD * HH];
__device__ float g_y  [BB * DD];
__device__ float g_hpart[BB * 8];
__device__ unsigned char g_valid[TOTAL];

// ---------------- helpers ----------------
__device__ __forceinline__ unsigned pack_h2(float lo, float hi) {
    __half2 p = __floats2half2_rn(lo, hi);
    return *reinterpret_cast<unsigned*>(&p);
}

__device__ __forceinline__ void mma_f16(float* c, const unsigned* a, const unsigned* b) {
    asm volatile(
        "mma.sync.aligned.m16n8k16.row.col.f32.f16.f16.f32 "
        "{%0,%1,%2,%3}, {%4,%5,%6,%7}, {%8,%9}, {%0,%1,%2,%3};\n"
        : "+f"(c[0]), "+f"(c[1]), "+f"(c[2]), "+f"(c[3])
        : "r"(a[0]), "r"(a[1]), "r"(a[2]), "r"(a[3]), "r"(b[0]), "r"(b[1]));
}

__device__ __forceinline__ void ldsm_x4(unsigned* r, unsigned addr) {
    asm volatile("ldmatrix.sync.aligned.m8n8.x4.shared.b16 {%0,%1,%2,%3}, [%4];"
                 : "=r"(r[0]), "=r"(r[1]), "=r"(r[2]), "=r"(r[3]) : "r"(addr));
}

__device__ __forceinline__ void cp16(void* smem_dst, const void* gsrc) {
    unsigned sdst = (unsigned)__cvta_generic_to_shared(smem_dst);
    asm volatile("cp.async.cg.shared.global [%0], [%1], 16;\n"
                 :: "r"(sdst), "l"(gsrc) : "memory");
}

#define CP_COMMIT() asm volatile("cp.async.commit_group;" ::: "memory")

// ---------------- fused gather + fp16 convert + valid mask ----------------
__global__ void zh_gather_kernel(const int* __restrict__ mut,
                                 const int* __restrict__ offs,
                                 const float* __restrict__ emb)
{
    int gid = blockIdx.x * blockDim.x + threadIdx.x;
    int r = gid >> 6;
    int c = (gid & 63) << 3;
    int b = r >> 10;
    int l = r & (LL - 1);
    int s = offs[b];
    int e = offs[b + 1];
    bool ok = l < (e - s);
    int t = ok ? mut[s + l] : 0;
    const float4* src = reinterpret_cast<const float4*>(emb + (size_t)t * DD + c);
    float4 v0 = src[0], v1 = src[1];
    uint4 o;
    o.x = pack_h2(v0.x, v0.y);
    o.y = pack_h2(v0.z, v0.w);
    o.z = pack_h2(v1.x, v1.y);
    o.w = pack_h2(v1.z, v1.w);
    *reinterpret_cast<uint4*>(g_zh + (size_t)r * DD + c) = o;
    if ((gid & 63) == 0) g_valid[r] = ok ? 1 : 0;
}

// ---------------- fused transpose of W1 and W2 ----------------
__global__ void wtrans2_kernel(const float* __restrict__ W1, __half* __restrict__ W1T,
                               const float* __restrict__ W2, __half* __restrict__ W2T)
{
    __shared__ float tile[32][33];
    const int tx = threadIdx.x, ty = threadIdx.y;
    int id = blockIdx.x;
    const float* W; __half* WT; int K, N, n0, k0;
    if (id < 1024) {
        W = W1; WT = W1T; K = DD; N = HH;
        n0 = (id & 63) * 32; k0 = (id >> 6) * 32;
    } else {
        id -= 1024;
        W = W2; WT = W2T; K = HH; N = DD;
        n0 = (id & 15) * 32; k0 = (id >> 4) * 32;
    }
#pragma unroll
    for (int i = 0; i < 4; i++)
        tile[ty + i * 8][tx] = W[(size_t)(k0 + ty + i * 8) * N + n0 + tx];
    __syncthreads();
#pragma unroll
    for (int i = 0; i < 4; i++)
        WT[(size_t)(n0 + ty + i * 8) * K + k0 + tx] = __float2half_rn(tile[tx][ty + i * 8]);
}

// ---------------- qp (4 blocks): qp = q @ Wq + bq ----------------
__global__ void __launch_bounds__(128)
qp_kernel(const float* __restrict__ q, const float* __restrict__ Wq,
          const float* __restrict__ bq)
{
    __shared__ float qs[DD];
    const int tid = threadIdx.x;
    for (int i = tid; i < DD; i += 128) qs[i] = q[i];
    __syncthreads();
    const int j = blockIdx.x * 128 + tid;
    float s = bq[j];
#pragma unroll 8
    for (int i = 0; i < DD; i++) s += qs[i] * Wq[(size_t)i * DD + j];
    g_qp[j] = s;
}

// ---------------- wk (8 blocks, one per head): wk_effH, c2k ----------------
__global__ void __launch_bounds__(512)
wk_kernel(const float* __restrict__ Wk, const float* __restrict__ bk,
          const float* __restrict__ b2)
{
    __shared__ float qph[HD];
    __shared__ float wk_s[DD];
    __shared__ float red[32];
    const int h = blockIdx.x;
    const int j = threadIdx.x;

    if (j < HD) qph[j] = g_qp[h * HD + j];
    __syncthreads();

    const float* wr = Wk + (size_t)j * DD + h * HD;
    float s = 0.f;
#pragma unroll
    for (int d = 0; d < HD; d++) s += wr[d] * qph[d];
    g_wk_effH[h * DD + j] = s;
    wk_s[j] = s;
    __syncthreads();

    // c2k[h] = bk_h . qp_h + b2 . wk_eff[:,h]
    float p = b2[j] * wk_s[j];
#pragma unroll
    for (int o = 16; o > 0; o >>= 1) p += __shfl_xor_sync(0xffffffffu, p, o);
    const int wid = j >> 5, lid = j & 31;
    if (lid == 0) red[wid] = p;
    __syncthreads();
    if (j == 0) {
        float c = 0.f;
        for (int w = 0; w < 16; w++) c += red[w];
        for (int d = 0; d < HD; d++) c += bk[h * HD + d] * qph[d];
        g_c2k[h] = c;
    }
}

// ---------------- prep2 (64 blocks): w2k coalesced warp-per-row (fp16 out) ----
__global__ void __launch_bounds__(256)
prep2_kernel(const float* __restrict__ W2)
{
    __shared__ float wk_h[NHEAD][DD];
    const int tid  = threadIdx.x;
    const int warp = tid >> 5;
    const int lane = tid & 31;

    for (int i = tid; i < NHEAD * DD; i += 256)
        (&wk_h[0][0])[i] = g_wk_effH[i];
    __syncthreads();

#pragma unroll
    for (int rr = 0; rr < 4; rr++) {
        const int i = blockIdx.x * 32 + warp * 4 + rr;
        const float* wr = W2 + (size_t)i * DD;
        float acc[NHEAD];
#pragma unroll
        for (int h = 0; h < NHEAD; h++) acc[h] = 0.f;
#pragma unroll
        for (int c = 0; c < 16; c++) {
            const int jj = lane + 32 * c;
            const float w = wr[jj];
#pragma unroll
            for (int h = 0; h < NHEAD; h++) acc[h] += w * wk_h[h][jj];
        }
#pragma unroll
        for (int h = 0; h < NHEAD; h++) {
#pragma unroll
            for (int o = 16; o > 0; o >>= 1)
                acc[h] += __shfl_xor_sync(0xffffffffu, acc[h], o);
        }
        if (lane == 0) {
#pragma unroll
            for (int h = 0; h < NHEAD; h++)
                g_w2kh[h * HH + i] = __float2half_rn(acc[h]);
        }
    }
}

// ---------------- fp16 GEMM (generic, optional split-K via blockIdx.z) --------
#define BK 64
#define ATILE 8192
#define STAGE (2 * ATILE)
#define NSTG 3
#define GSMEM (NSTG * STAGE * 2)   // 98304 B

template<bool HOUT, bool RELU>
__global__ void __launch_bounds__(256, 2)
f16_gemm_kernel(const __half* __restrict__ A,
                const __half* __restrict__ Bt,
                const float* __restrict__ bias, void* __restrict__ Cv,
                int N, int K, int kLen, int pstride)
{
    extern __shared__ __align__(16) __half sm[];

    const int tid  = threadIdx.x;
    const int bm   = blockIdx.y * 128;
    const int bn   = blockIdx.x * 128;
    const int kz   = blockIdx.z;
    const int koff = kz * kLen;
    const int warp = tid >> 5;
    const int lane = tid & 31;
    const int lm   = lane >> 2;
    const int lk   = lane & 3;
    const int wm   = (warp >> 2) * 64;
    const int wn   = (warp & 3) * 32;

    const unsigned smem_b = (unsigned)__cvta_generic_to_shared(sm);

    const int lrow = tid >> 3;
    const int lchk = tid & 7;
    const __half* aptr[4];
    const __half* bptr[4];
    int adst[4];
#pragma unroll
    for (int p = 0; p < 4; p++) {
        const int r = lrow + p * 32;
        aptr[p] = A  + (size_t)(bm + r) * K + koff + lchk * 8;
        bptr[p] = Bt + (size_t)(bn + r) * K + koff + lchk * 8;
        adst[p] = r * BK + ((lchk ^ (r & 7)) * 8);
    }

    int a_off[4], a_sw[4];
#pragma unroll
    for (int mt = 0; mt < 4; mt++) {
        const int r = wm + mt * 16 + (lane & 15);
        a_off[mt] = r * 128;
        a_sw[mt]  = r & 7;
    }
    const int a_hi = (lane >> 4) & 1;
    int b_off[2], b_sw[2];
#pragma unroll
    for (int pr = 0; pr < 2; pr++) {
        const int n = wn + pr * 16 + (lane & 7) + (((lane >> 4) & 1) << 3);
        b_off[pr] = n * 128;
        b_sw[pr]  = n & 7;
    }
    const int b_hi = (lane >> 3) & 1;

    float acc[4][4][4];
#pragma unroll
    for (int mt = 0; mt < 4; mt++)
#pragma unroll
        for (int nt = 0; nt < 4; nt++)
#pragma unroll
            for (int r = 0; r < 4; r++) acc[mt][nt][r] = 0.f;

    const int T = kLen / BK;

    auto load_stage = [&](int s, int t) {
        __half* As = sm + s * STAGE;
        __half* Bs = As + ATILE;
        const int kt = t * BK;
#pragma unroll
        for (int p = 0; p < 4; p++) cp16(As + adst[p], aptr[p] + kt);
#pragma unroll
        for (int p = 0; p < 4; p++) cp16(Bs + adst[p], bptr[p] + kt);
        CP_COMMIT();
    };

    load_stage(0, 0);
    load_stage(1, 1);
    asm volatile("cp.async.wait_group 1;" ::: "memory");
    __syncthreads();

    for (int t = 0; t < T; t++) {
        const int s = t % NSTG;
        if (t + 2 < T) load_stage((t + 2) % NSTG, t + 2);

        const unsigned abase = smem_b + s * (STAGE * 2);
        const unsigned bbase = abase + ATILE * 2;
#pragma unroll
        for (int kk = 0; kk < 4; kk++) {
            const int ca = 2 * kk + a_hi;
            const int cb = 2 * kk + b_hi;
            unsigned bf[2][4];
#pragma unroll
            for (int pr = 0; pr < 2; pr++)
                ldsm_x4(bf[pr], bbase + b_off[pr] + ((cb ^ b_sw[pr]) << 4));
            unsigned af[4][4];
#pragma unroll
            for (int mt = 0; mt < 4; mt++)
                ldsm_x4(af[mt], abase + a_off[mt] + ((ca ^ a_sw[mt]) << 4));
#pragma unroll
            for (int mt = 0; mt < 4; mt++)
#pragma unroll
                for (int pr = 0; pr < 2; pr++) {
                    mma_f16(acc[mt][2 * pr],     af[mt], &bf[pr][0]);
                    mma_f16(acc[mt][2 * pr + 1], af[mt], &bf[pr][2]);
                }
        }

        if (t + 2 < T)
            asm volatile("cp.async.wait_group 1;" ::: "memory");
        else
            asm volatile("cp.async.wait_group 0;" ::: "memory");
        __syncthreads();
    }

    const float bsc = (kz == 0) ? 1.f : 0.f;
#pragma unroll
    for (int mt = 0; mt < 4; mt++) {
        const int row = bm + wm + mt * 16 + lm;
#pragma unroll
        for (int nt = 0; nt < 4; nt++) {
            const int col = bn + wn + nt * 8 + lk * 2;
            const float2 bia = *reinterpret_cast<const float2*>(&bias[col]);
            float r0x = acc[mt][nt][0] + bia.x * bsc;
            float r0y = acc[mt][nt][1] + bia.y * bsc;
            float r1x = acc[mt][nt][2] + bia.x * bsc;
            float r1y = acc[mt][nt][3] + bia.y * bsc;
            if (RELU) {
                r0x = fmaxf(r0x, 0.f); r0y = fmaxf(r0y, 0.f);
                r1x = fmaxf(r1x, 0.f); r1y = fmaxf(r1y, 0.f);
            }
            if (HOUT) {
                __half* C = (__half*)Cv;
                *reinterpret_cast<unsigned*>(C + (size_t)row * N + col)       = pack_h2(r0x, r0y);
                *reinterpret_cast<unsigned*>(C + (size_t)(row + 8) * N + col) = pack_h2(r1x, r1y);
            } else {
                float* C = (float*)Cv + (size_t)kz * pstride;
                *reinterpret_cast<float2*>(C + (size_t)row * N + col)       = make_float2(r0x, r0y);
                *reinterpret_cast<float2*>(C + (size_t)(row + 8) * N + col) = make_float2(r1x, r1y);
            }
        }
    }
}

// ---------------- block reductions ----------------
__device__ __forceinline__ float block_sum(float v, float* red) {
#pragma unroll
    for (int o = 16; o > 0; o >>= 1) v += __shfl_xor_sync(0xffffffffu, v, o);
    const int wid = threadIdx.x >> 5, lid = threadIdx.x & 31;
    const int nw = blockDim.x >> 5;
    if (lid == 0) red[wid] = v;
    __syncthreads();
    if (wid == 0) {
        v = (lid < nw) ? red[lid] : 0.f;
#pragma unroll
        for (int o = 16; o > 0; o >>= 1) v += __shfl_xor_sync(0xffffffffu, v, o);
        if (lid == 0) red[0] = v;
    }
    __syncthreads();
    float r = red[0];
    __syncthreads();
    return r;
}

__device__ __forceinline__ float block_max(float v, float* red) {
#pragma unroll
    for (int o = 16; o > 0; o >>= 1) v = fmaxf(v, __shfl_xor_sync(0xffffffffu, v, o));
    const int wid = threadIdx.x >> 5, lid = threadIdx.x & 31;
    const int nw = blockDim.x >> 5;
    if (lid == 0) red[wid] = v;
    __syncthreads();
    if (wid == 0) {
        v = (lid < nw) ? red[lid] : -3.4e38f;
#pragma unroll
        for (int o = 16; o > 0; o >>= 1) v = fmaxf(v, __shfl_xor_sync(0xffffffffu, v, o));
        if (lid == 0) red[0] = v;
    }
    __syncthreads();
    float r = red[0];
    __syncthreads();
    return r;
}

// ---------------- scores: 4 rows/warp, uint4 hidh loads ----------------
__global__ void __launch_bounds__(256)
scores2_kernel()
{
    __shared__ __half2 w2k_s[NHEAD][HH / 2];  // 32 KB
    __shared__ float c2k_s[NHEAD];
    const int tid  = threadIdx.x;
    const int warp = tid >> 5;
    const int lane = tid & 31;

    for (int i = tid; i < NHEAD * HH / 2; i += 256)
        (&w2k_s[0][0])[i] = reinterpret_cast<const __half2*>(g_w2kh)[i];
    if (tid < NHEAD) c2k_s[tid] = g_c2k[tid];
    __syncthreads();

    const int row0 = blockIdx.x * 128;
    for (int it = 0; it < 4; it++) {
        const int rbase = row0 + it * 32 + warp * 4;
        const uint4* hp4 = reinterpret_cast<const uint4*>(g_hidh + (size_t)rbase * HH);
        float acc[4][NHEAD];
#pragma unroll
        for (int rr = 0; rr < 4; rr++)
#pragma unroll
            for (int h = 0; h < NHEAD; h++) acc[rr][h] = 0.f;

        for (int c = 0; c < 8; c++) {
            const int u = lane + 32 * c;      // uint4 index 0..255 (256 per row)
            float2 wf[NHEAD][4];
#pragma unroll
            for (int h = 0; h < NHEAD; h++)
#pragma unroll
                for (int qq = 0; qq < 4; qq++)
                    wf[h][qq] = __half22float2(w2k_s[h][u * 4 + qq]);
#pragma unroll
            for (int rr = 0; rr < 4; rr++) {
                const uint4 hv = hp4[(size_t)rr * 256 + u];
                const unsigned hw[4] = {hv.x, hv.y, hv.z, hv.w};
#pragma unroll
                for (int qq = 0; qq < 4; qq++) {
                    const float2 hf = __half22float2(
                        *reinterpret_cast<const __half2*>(&hw[qq]));
#pragma unroll
                    for (int h = 0; h < NHEAD; h++)
                        acc[rr][h] = fmaf(hf.x, wf[h][qq].x,
                                     fmaf(hf.y, wf[h][qq].y, acc[rr][h]));
                }
            }
        }
#pragma unroll
        for (int rr = 0; rr < 4; rr++) {
#pragma unroll
            for (int h = 0; h < NHEAD; h++) {
#pragma unroll
                for (int o = 16; o > 0; o >>= 1)
                    acc[rr][h] += __shfl_xor_sync(0xffffffffu, acc[rr][h], o);
            }
            if (lane < NHEAD) {
                const int row = rbase + rr;
                const int b = row >> 10;
                const int l = row & (LL - 1);
                float s = (acc[rr][lane] + c2k_s[lane]) * 0.125f;
                if (!g_valid[row]) s = -1e30f;
                g_s[(b * NHEAD + lane) * LL + l] = s;
            }
        }
    }
}

// ---------------- softmax ----------------
__global__ void softmax_kernel()
{
    const int bh = blockIdx.x;
    const int tid = threadIdx.x;
    __shared__ float red[32];
    float* sp = g_s + (size_t)bh * LL;

    float v0 = sp[tid], v1 = sp[tid + 256], v2 = sp[tid + 512], v3 = sp[tid + 768];
    float mx = fmaxf(fmaxf(v0, v1), fmaxf(v2, v3));
    mx = block_max(mx, red);
    float e0 = __expf(v0 - mx), e1 = __expf(v1 - mx);
    float e2 = __expf(v2 - mx), e3 = __expf(v3 - mx);
    float sum = block_sum(e0 + e1 + e2 + e3, red);
    const float inv = 1.f / sum;
    sp[tid] = e0 * inv; sp[tid + 256] = e1 * inv;
    sp[tid + 512] = e2 * inv; sp[tid + 768] = e3 * inv;
}

// ---------------- hidbar partials: grid (BB,8), 512 thr, unrolled -------------
__global__ void __launch_bounds__(512)
hidbar_kernel()
{
    const int b  = blockIdx.x;
    const int ch = blockIdx.y;
    const int tid = threadIdx.x;
    const int d0 = tid * 4;
    __shared__ float a_s[NHEAD][128];

    for (int i = tid; i < NHEAD * 128; i += 512) {
        const int h = i >> 7, l = i & 127;
        a_s[h][l] = g_s[(size_t)(b * NHEAD + h) * LL + ch * 128 + l];
    }
    __syncthreads();

    float acc[NHEAD][4];
#pragma unroll
    for (int h = 0; h < NHEAD; h++)
#pragma unroll
        for (int e = 0; e < 4; e++) acc[h][e] = 0.f;

    const __half* hp = g_hidh + ((size_t)(b * LL + ch * 128)) * HH + d0;
#pragma unroll 4
    for (int l = 0; l < 128; l++) {
        const uint2 hv = *reinterpret_cast<const uint2*>(hp + (size_t)l * HH);
        float f[4];
        {
            float2 t;
            t = __half22float2(*reinterpret_cast<const __half2*>(&hv.x)); f[0]=t.x; f[1]=t.y;
            t = __half22float2(*reinterpret_cast<const __half2*>(&hv.y)); f[2]=t.x; f[3]=t.y;
        }
#pragma unroll
        for (int h = 0; h < NHEAD; h++) {
            const float a = a_s[h][l];
#pragma unroll
            for (int e = 0; e < 4; e++) acc[h][e] += a * f[e];
        }
    }
#pragma unroll
    for (int h = 0; h < NHEAD; h++)
#pragma unroll
        for (int e = 0; e < 4; e++)
            g_hbp[((size_t)(ch * BB * NHEAD) + b * NHEAD + h) * HH + d0 + e] = acc[h][e];
}

// ---------------- reduce hidbar partials (8) -> fp16 ----------------
__global__ void hbred_kernel()
{
    const int idx = blockIdx.x * blockDim.x + threadIdx.x;
    float s = 0.f;
#pragma unroll
    for (int c = 0; c < 8; c++)
        s += g_hbp[(size_t)c * BB * NHEAD * HH + idx];
    g_hidbarh[idx] = __float2half_rn(s);
}

// ---------------- fused ctx + pooled + LN (sums 4 split-K partials) -----------
__global__ void __launch_bounds__(512)
ctx_pooled_ln_kernel(const float* __restrict__ Wv, const float* __restrict__ bv,
                     const float* __restrict__ Wo, const float* __restrict__ bo,
                     const float* __restrict__ ln_g, const float* __restrict__ ln_b)
{
    const int b = blockIdx.x;
    const int j = threadIdx.x;
    __shared__ float hb[NHEAD][DD];
    __shared__ float cx[DD];
    __shared__ float red[32];

    const int psz = BB * NHEAD * DD;
    for (int i = j; i < NHEAD * DD; i += 512) {
        float s = 0.f;
#pragma unroll
        for (int c = 0; c < 4; c++)
            s += g_hbp[(size_t)c * psz + b * NHEAD * DD + i];
        (&hb[0][0])[i] = s;
    }
    __syncthreads();

    const int h = j >> 6;
    float s = bv[j];
    for (int i = 0; i < DD; i++) s += hb[h][i] * Wv[(size_t)i * DD + j];
    cx[j] = s;
    __syncthreads();

    float p = bo[j];
    for (int i = 0; i < DD; i++) p += cx[i] * Wo[(size_t)i * DD + j];

    const float mu = block_sum(p, red) * (1.f / DD);
    float dv = p - mu;
    const float var = block_sum(dv * dv, red) * (1.f / DD);
    const float rstd = rsqrtf(var + 1e-5f);
    g_y[b * DD + j] = dv * rstd * ln_g[j] + ln_b[j];
}

// ---------------- head ----------------
__global__ void head1_kernel(const float* __restrict__ Wh1, const float* __restrict__ bh1,
                             const float* __restrict__ Wh2)
{
    const int b = blockIdx.x;
    const int sl = blockIdx.y;
    const int tid = threadIdx.x;
    __shared__ float y[DD];
    __shared__ float red[32];

    y[tid]       = g_y[b * DD + tid];
    y[tid + 256] = g_y[b * DD + tid + 256];
    __syncthreads();

    const int j = sl * 256 + tid;
    float t = bh1[j];
    for (int i = 0; i < DD; i++) t += y[i] * Wh1[(size_t)i * HH + j];
    float p = fmaxf(t, 0.f) * Wh2[j];
    const float tot = block_sum(p, red);
    if (tid == 0) g_hpart[b * 8 + sl] = tot;
}

__global__ void head2_kernel(const float* __restrict__ bh2, float* __restrict__ out)
{
    const int b = threadIdx.x;
    float s = bh2[0];
#pragma unroll
    for (int i = 0; i < 8; i++) s += g_hpart[b * 8 + i];
    out[b] = s;
}

// ---------------- launcher ----------------
extern "C" void kernel_launch(void* const* d_in, const int* in_sizes, int n_in,
                              void* d_out, int out_size)
{
    const int*   mut  = (const int*)d_in[0];
    const int*   offs = (const int*)d_in[1];
    const float* emb  = (const float*)d_in[2];
    const float* W1   = (const float*)d_in[3];
    const float* b1   = (const float*)d_in[4];
    const float* W2   = (const float*)d_in[5];
    const float* b2   = (const float*)d_in[6];
    const float* q    = (const float*)d_in[7];
    const float* Wq   = (const float*)d_in[8];
    const float* bq   = (const float*)d_in[9];
    const float* Wk   = (const float*)d_in[10];
    const float* bk   = (const float*)d_in[11];
    const float* Wv   = (const float*)d_in[12];
    const float* bv   = (const float*)d_in[13];
    const float* Wo   = (const float*)d_in[14];
    const float* bo   = (const float*)d_in[15];
    const float* ln_g = (const float*)d_in[16];
    const float* ln_b = (const float*)d_in[17];
    const float* Wh1  = (const float*)d_in[18];
    const float* bh1  = (const float*)d_in[19];
    const float* Wh2  = (const float*)d_in[20];
    const float* bh2  = (const float*)d_in[21];
    float* out = (float*)d_out;

    void *p_zh, *p_hidh, *p_w1t, *p_w2t, *p_hbh, *p_hbp;
    cudaGetSymbolAddress(&p_zh,   g_zh);
    cudaGetSymbolAddress(&p_hidh, g_hidh);
    cudaGetSymbolAddress(&p_w1t,  g_w1t);
    cudaGetSymbolAddress(&p_w2t,  g_w2t);
    cudaGetSymbolAddress(&p_hbh,  g_hidbarh);
    cudaGetSymbolAddress(&p_hbp,  g_hbp);
    __half* zh   = (__half*)p_zh;
    __half* hidh = (__half*)p_hidh;
    __half* w1t  = (__half*)p_w1t;
    __half* w2t  = (__half*)p_w2t;
    __half* hbh  = (__half*)p_hbh;
    float*  hbp  = (float*)p_hbp;

    cudaFuncSetAttribute(f16_gemm_kernel<true, true>,
                         cudaFuncAttributeMaxDynamicSharedMemorySize, GSMEM);
    cudaFuncSetAttribute(f16_gemm_kernel<false, false>,
                         cudaFuncAttributeMaxDynamicSharedMemorySize, GSMEM);

    // single stream; big GEMM at launch index 3 (ncu capture slot)
    wtrans2_kernel<<<2048, dim3(32, 8)>>>(W1, w1t, W2, w2t);
    zh_gather_kernel<<<(TOTAL * 64) / 256, 256>>>(mut, offs, emb);
    qp_kernel<<<DD / 128, 128>>>(q, Wq, bq);

    // 3) hidh = f16(relu(zh @ W1 + b1))  [65536 x 2048], K=512
    f16_gemm_kernel<true, true><<<dim3(HH / 128, TOTAL / 128, 1), 256, GSMEM>>>(
        zh, w1t, b1, hidh, HH, DD, DD, 0);

    wk_kernel<<<NHEAD, 512>>>(Wk, bk, b2);
    prep2_kernel<<<HH / 32, 256>>>(W2);

    scores2_kernel<<<TOTAL / 128, 256>>>();
    softmax_kernel<<<BB * NHEAD, 256>>>();

    hidbar_kernel<<<dim3(BB, 8), 512>>>();
    hbred_kernel<<<(BB * NHEAD * HH) / 256, 256>>>();

    // hbar = hidbar @ W2 + b2  — split-K x4 (fp32 partials into g_hbp)
    f16_gemm_kernel<false, false><<<dim3(DD / 128, (BB * NHEAD) / 128, 4), 256, GSMEM>>>(
        hbh, w2t, b2, hbp, DD, HH, HH / 4, BB * NHEAD * DD);

    ctx_pooled_ln_kernel<<<BB, DD>>>(Wv, bv, Wo, bo, ln_g, ln_b);
    head1_kernel<<<dim3(BB, 8), 256>>>(Wh1, bh1, Wh2);
    head2_kernel<<<1, BB>>>(bh2, out);
}